// round 1
// baseline (speedup 1.0000x reference)
#include <cuda_runtime.h>
#include <math.h>

#define N_NODES 100000
#define D_FEAT  128
#define E_EDGES 600000
#define C_OUT   256

// ---------------- scratch (no allocs allowed; __device__ globals) -------------
__device__ float g_sums[(size_t)N_NODES * D_FEAT];   // 51.2 MB
__device__ float g_cnt[N_NODES];
__device__ int   g_idx64;                            // 1 if edge_index is int64

// ---------------- index-width detection --------------------------------------
// If the buffer is really int32, an int64 read combines two random values in
// [0,1e5): v = lo + hi*2^32 >= 2^32 unless hi==0 (p ~ 1e-5 per element).
// Checking 8 elements makes misdetection probability ~1e-40.
__global__ void detect_kernel(const long long* __restrict__ ei) {
    int ok = 1;
#pragma unroll
    for (int i = 0; i < 8; i++) {
        long long v = ei[i];            // safe: first 8 int64 words exist either way
        if (v < 0 || v >= (long long)N_NODES) ok = 0;
    }
    g_idx64 = ok;
}

// ---------------- zero scratch ------------------------------------------------
__global__ void zero_kernel() {
    int i = blockIdx.x * blockDim.x + threadIdx.x;
    const int TOT4 = N_NODES * D_FEAT / 4;   // 3.2M float4
    if (i < TOT4) reinterpret_cast<float4*>(g_sums)[i] = make_float4(0.f, 0.f, 0.f, 0.f);
    if (i < N_NODES) g_cnt[i] = 0.f;
}

// ---------------- edge scatter: one warp per edge ----------------------------
__global__ void scatter_kernel(const float* __restrict__ x,
                               const long long* __restrict__ ei) {
    int gid  = blockIdx.x * blockDim.x + threadIdx.x;
    int e    = gid >> 5;
    int lane = gid & 31;
    if (e >= E_EDGES) return;

    long long r, c;
    if (g_idx64) {
        r = ei[e];
        c = ei[E_EDGES + e];
    } else {
        const int* e32 = (const int*)ei;
        r = e32[e];
        c = e32[E_EDGES + e];
    }
    if (r == c) return;   // self-loop removal

    const float4 v = *reinterpret_cast<const float4*>(x + (size_t)c * D_FEAT + lane * 4);
    float* dst = g_sums + (size_t)r * D_FEAT + lane * 4;
    atomicAdd(dst + 0, v.x);
    atomicAdd(dst + 1, v.y);
    atomicAdd(dst + 2, v.z);
    atomicAdd(dst + 3, v.w);
    if (lane == 0) atomicAdd(&g_cnt[r], 1.0f);
}

// ---------------- fused (mean || x) @ W + bias -------------------------------
// Tile: BM=64 nodes x BN=64 cols, BK=16, 256 threads (16x16), 4x4 per thread.
// A[m][k] = k<128 ? sums[m][k]/max(cnt,1) : x[m][k-128], computed in the tile load.
#define BM 64
#define BN 64
#define BK 16

__global__ __launch_bounds__(256) void gemm_kernel(const float* __restrict__ x,
                                                   const float* __restrict__ W,
                                                   const float* __restrict__ bias,
                                                   float* __restrict__ out) {
    __shared__ float As[BK][BM + 1];   // [k][m], +1 pad to spread store banks
    __shared__ float Bs[BK][BN];       // [k][n]

    const int tid = threadIdx.x;
    const int tx = tid & 15;           // 0..15 -> output col group
    const int ty = tid >> 4;           // 0..15 -> output row group
    const int node0 = blockIdx.x * BM;
    const int c0    = blockIdx.y * BN;

    float acc[4][4];
#pragma unroll
    for (int i = 0; i < 4; i++)
#pragma unroll
        for (int j = 0; j < 4; j++) acc[i][j] = 0.f;

    for (int k0 = 0; k0 < 2 * D_FEAT; k0 += BK) {
        // --- load A tile (transposed into As[k][m]) ---
        {
            int m  = tid >> 2;            // 0..63
            int kq = (tid & 3) * 4;       // 0,4,8,12
            int mg = node0 + m;
            float4 v = make_float4(0.f, 0.f, 0.f, 0.f);
            if (mg < N_NODES) {
                int k = k0 + kq;
                if (k < D_FEAT) {
                    v = *reinterpret_cast<const float4*>(g_sums + (size_t)mg * D_FEAT + k);
                    float inv = 1.0f / fmaxf(g_cnt[mg], 1.0f);
                    v.x *= inv; v.y *= inv; v.z *= inv; v.w *= inv;
                } else {
                    v = *reinterpret_cast<const float4*>(x + (size_t)mg * D_FEAT + (k - D_FEAT));
                }
            }
            As[kq + 0][m] = v.x;
            As[kq + 1][m] = v.y;
            As[kq + 2][m] = v.z;
            As[kq + 3][m] = v.w;
        }
        // --- load B tile ---
        {
            int r  = tid >> 4;            // 0..15
            int cq = (tid & 15) * 4;      // 0..60
            float4 w = *reinterpret_cast<const float4*>(W + (size_t)(k0 + r) * C_OUT + c0 + cq);
            *reinterpret_cast<float4*>(&Bs[r][cq]) = w;
        }
        __syncthreads();

#pragma unroll
        for (int kk = 0; kk < BK; kk++) {
            float a0 = As[kk][ty * 4 + 0];
            float a1 = As[kk][ty * 4 + 1];
            float a2 = As[kk][ty * 4 + 2];
            float a3 = As[kk][ty * 4 + 3];
            float4 b = *reinterpret_cast<float4*>(&Bs[kk][tx * 4]);
            acc[0][0] += a0 * b.x; acc[0][1] += a0 * b.y; acc[0][2] += a0 * b.z; acc[0][3] += a0 * b.w;
            acc[1][0] += a1 * b.x; acc[1][1] += a1 * b.y; acc[1][2] += a1 * b.z; acc[1][3] += a1 * b.w;
            acc[2][0] += a2 * b.x; acc[2][1] += a2 * b.y; acc[2][2] += a2 * b.z; acc[2][3] += a2 * b.w;
            acc[3][0] += a3 * b.x; acc[3][1] += a3 * b.y; acc[3][2] += a3 * b.z; acc[3][3] += a3 * b.w;
        }
        __syncthreads();
    }

    // --- epilogue: + bias, store ---
    float4 bv = *reinterpret_cast<const float4*>(bias + c0 + tx * 4);
#pragma unroll
    for (int i = 0; i < 4; i++) {
        int mg = node0 + ty * 4 + i;
        if (mg < N_NODES) {
            float4 o;
            o.x = acc[i][0] + bv.x;
            o.y = acc[i][1] + bv.y;
            o.z = acc[i][2] + bv.z;
            o.w = acc[i][3] + bv.w;
            *reinterpret_cast<float4*>(out + (size_t)mg * C_OUT + c0 + tx * 4) = o;
        }
    }
}

// ---------------- row L2 normalize: one warp per node ------------------------
__global__ void norm_kernel(float* __restrict__ out) {
    int gid  = blockIdx.x * blockDim.x + threadIdx.x;
    int node = gid >> 5;
    int lane = gid & 31;
    if (node >= N_NODES) return;

    float4* p = reinterpret_cast<float4*>(out + (size_t)node * C_OUT);
    float4 v0 = p[lane];
    float4 v1 = p[lane + 32];
    float ss = v0.x * v0.x + v0.y * v0.y + v0.z * v0.z + v0.w * v0.w
             + v1.x * v1.x + v1.y * v1.y + v1.z * v1.z + v1.w * v1.w;
#pragma unroll
    for (int off = 16; off > 0; off >>= 1)
        ss += __shfl_xor_sync(0xFFFFFFFFu, ss, off);

    float inv = 1.0f / fmaxf(sqrtf(ss), 1e-12f);
    v0.x *= inv; v0.y *= inv; v0.z *= inv; v0.w *= inv;
    v1.x *= inv; v1.y *= inv; v1.z *= inv; v1.w *= inv;
    p[lane]      = v0;
    p[lane + 32] = v1;
}

// ---------------- launch ------------------------------------------------------
extern "C" void kernel_launch(void* const* d_in, const int* in_sizes, int n_in,
                              void* d_out, int out_size) {
    const float*     x    = (const float*)d_in[0];      // [100000,128]
    const long long* ei   = (const long long*)d_in[1];  // [2,600000] (int64 or int32, detected)
    const float*     W    = (const float*)d_in[2];      // [256,256]
    const float*     bias = (const float*)d_in[3];      // [1,256]
    float*           out  = (float*)d_out;              // [100000,256]

    detect_kernel<<<1, 1>>>(ei);

    {
        int tot = N_NODES * D_FEAT / 4;                 // 3.2M (>= N_NODES)
        zero_kernel<<<(tot + 255) / 256, 256>>>();
    }

    {
        long long threads = (long long)E_EDGES * 32;
        scatter_kernel<<<(int)((threads + 255) / 256), 256>>>(x, ei);
    }

    {
        dim3 grid((N_NODES + BM - 1) / BM, C_OUT / BN); // 1563 x 4
        gemm_kernel<<<grid, 256>>>(x, W, bias, out);
    }

    {
        long long threads = (long long)N_NODES * 32;
        norm_kernel<<<(int)((threads + 255) / 256), 256>>>(out);
    }
}

// round 4
// speedup vs baseline: 1.5508x; 1.5508x over previous
#include <cuda_runtime.h>
#include <math.h>

#define N_NODES 100000
#define D_FEAT  128
#define E_EDGES 600000
#define C_OUT   256
#define K_TOT   256

// ---------------- scratch (no allocs allowed; __device__ globals) -------------
__device__ __align__(16) float g_sums[(size_t)N_NODES * D_FEAT];   // 51.2 MB
__device__ float g_cnt[N_NODES];
__device__ int   g_idx64;                            // 1 if edge_index is int64

// ---------------- index-width detection --------------------------------------
// If the buffer is really int32, an int64 read combines two random ints in
// [0,1e5): v = lo + hi*2^32 >= 2^32 unless hi==0 (p ~ 1e-5 per element).
__global__ void detect_kernel(const long long* __restrict__ ei) {
    int ok = 1;
#pragma unroll
    for (int i = 0; i < 8; i++) {
        long long v = ei[i];
        if (v < 0 || v >= (long long)N_NODES) ok = 0;
    }
    g_idx64 = ok;
}

// ---------------- zero scratch ------------------------------------------------
__global__ void zero_kernel() {
    int i = blockIdx.x * blockDim.x + threadIdx.x;
    const int TOT4 = N_NODES * D_FEAT / 4;   // 3.2M float4
    if (i < TOT4) reinterpret_cast<float4*>(g_sums)[i] = make_float4(0.f, 0.f, 0.f, 0.f);
    if (i < N_NODES) g_cnt[i] = 0.f;
}

// ---------------- vector reduction helper ------------------------------------
__device__ __forceinline__ void red_add_v4(float* p, float4 v) {
    asm volatile("red.global.add.v4.f32 [%0], {%1, %2, %3, %4};"
                 :: "l"(p), "f"(v.x), "f"(v.y), "f"(v.z), "f"(v.w)
                 : "memory");
}

// ---------------- edge scatter: one warp per edge, one RED.128 per lane ------
__global__ void scatter_kernel(const float* __restrict__ x,
                               const long long* __restrict__ ei) {
    int gid  = blockIdx.x * blockDim.x + threadIdx.x;
    int e    = gid >> 5;
    int lane = gid & 31;
    if (e >= E_EDGES) return;

    int r, c;
    if (g_idx64) {
        r = (int)ei[e];
        c = (int)ei[E_EDGES + e];
    } else {
        const int* e32 = (const int*)ei;
        r = e32[e];
        c = e32[E_EDGES + e];
    }
    if (r == c) return;   // self-loop removal

    const float4 v = *reinterpret_cast<const float4*>(x + (size_t)c * D_FEAT + lane * 4);
    red_add_v4(g_sums + (size_t)r * D_FEAT + lane * 4, v);
    if (lane == 0) atomicAdd(&g_cnt[r], 1.0f);
}

// ---------------- fused (mean || x) @ W + bias + row-L2-normalize ------------
// Block tile: BM=64 nodes x BN=256 (full output row), BK=16, 256 threads.
// Thread tile 8x8. ty = tid>>5 (8 row-groups), tx = tid&31 (32 col-groups).
// Threads sharing ty form one warp -> warp-shfl row norm in the epilogue.
#define BM 64
#define BK 16
#define APAD 4            // row stride 68 floats = 272B: 16B-aligned, 2-way-max bank conflict on store
#define NT (K_TOT / BK)   // 16 k-tiles

__global__ __launch_bounds__(256, 2) void gemm_kernel(const float* __restrict__ x,
                                                      const float* __restrict__ W,
                                                      const float* __restrict__ bias,
                                                      float* __restrict__ out) {
    __shared__ __align__(16) float As[2][BK][BM + APAD];   // [buf][k][m]
    __shared__ __align__(16) float Bs[2][BK][C_OUT];       // [buf][k][n]

    const int tid = threadIdx.x;
    const int tx  = tid & 31;             // col group: cols tx*8 .. tx*8+7
    const int ty  = tid >> 5;             // row group: rows ty*8 .. ty*8+7 (== warp id)
    const int node0 = blockIdx.x * BM;

    // A-load role: thread handles row am, k-quad akq (4 consecutive k)
    const int am  = tid >> 2;             // 0..63
    const int akq = (tid & 3) * 4;        // 0,4,8,12
    const int amg = node0 + am;
    const bool a_ok = (amg < N_NODES);
    float inv_cnt = 1.0f;
    if (a_ok) inv_cnt = 1.0f / fmaxf(g_cnt[amg], 1.0f);

    float acc[8][8];
#pragma unroll
    for (int i = 0; i < 8; i++)
#pragma unroll
        for (int j = 0; j < 8; j++) acc[i][j] = 0.f;

    // ---- tile fetch helpers (to registers) ----
    float4 aReg;            // A: 1 float4 per thread
    float4 bReg[4];         // B: 4 float4 per thread

    auto fetch = [&](int t) {
        int k = t * BK + akq;
        if (a_ok) {
            if (k < D_FEAT) {
                aReg = *reinterpret_cast<const float4*>(g_sums + (size_t)amg * D_FEAT + k);
                aReg.x *= inv_cnt; aReg.y *= inv_cnt; aReg.z *= inv_cnt; aReg.w *= inv_cnt;
            } else {
                aReg = *reinterpret_cast<const float4*>(x + (size_t)amg * D_FEAT + (k - D_FEAT));
            }
        } else {
            aReg = make_float4(0.f, 0.f, 0.f, 0.f);
        }
#pragma unroll
        for (int j = 0; j < 4; j++) {
            int f  = j * 256 + tid;       // float4 index in 16x256 tile (coalesced)
            int kk = f >> 6;
            int n4 = f & 63;
            bReg[j] = *reinterpret_cast<const float4*>(W + (size_t)(t * BK + kk) * C_OUT + n4 * 4);
        }
    };
    auto stage = [&](int b) {
        As[b][akq + 0][am] = aReg.x;
        As[b][akq + 1][am] = aReg.y;
        As[b][akq + 2][am] = aReg.z;
        As[b][akq + 3][am] = aReg.w;
#pragma unroll
        for (int j = 0; j < 4; j++) {
            int f  = j * 256 + tid;
            int kk = f >> 6;
            int n4 = f & 63;
            *reinterpret_cast<float4*>(&Bs[b][kk][n4 * 4]) = bReg[j];
        }
    };

    // ---- pipeline: prologue ----
    fetch(0);
    stage(0);
    __syncthreads();

    int buf = 0;
#pragma unroll 1
    for (int t = 0; t < NT; t++) {
        if (t + 1 < NT) fetch(t + 1);

        // compute on buf
#pragma unroll
        for (int kk = 0; kk < BK; kk++) {
            float4 a0 = *reinterpret_cast<float4*>(&As[buf][kk][ty * 8]);
            float4 a1 = *reinterpret_cast<float4*>(&As[buf][kk][ty * 8 + 4]);
            float4 b0 = *reinterpret_cast<float4*>(&Bs[buf][kk][tx * 8]);
            float4 b1 = *reinterpret_cast<float4*>(&Bs[buf][kk][tx * 8 + 4]);
            float av[8] = {a0.x, a0.y, a0.z, a0.w, a1.x, a1.y, a1.z, a1.w};
            float bv[8] = {b0.x, b0.y, b0.z, b0.w, b1.x, b1.y, b1.z, b1.w};
#pragma unroll
            for (int i = 0; i < 8; i++)
#pragma unroll
                for (int j = 0; j < 8; j++)
                    acc[i][j] += av[i] * bv[j];
        }

        if (t + 1 < NT) {
            stage(buf ^ 1);
            __syncthreads();
            buf ^= 1;
        }
    }

    // ---- epilogue: + bias, row L2 norm (warp owns rows ty*8..+7), store ----
    float4 bv0 = *reinterpret_cast<const float4*>(bias + tx * 8);
    float4 bv1 = *reinterpret_cast<const float4*>(bias + tx * 8 + 4);
    float bb[8] = {bv0.x, bv0.y, bv0.z, bv0.w, bv1.x, bv1.y, bv1.z, bv1.w};

    float ss[8];
#pragma unroll
    for (int i = 0; i < 8; i++) {
        float s = 0.f;
#pragma unroll
        for (int j = 0; j < 8; j++) {
            acc[i][j] += bb[j];
            s += acc[i][j] * acc[i][j];
        }
        ss[i] = s;
    }
    // warp reduction across the 32 tx-threads (whole 256-col row)
#pragma unroll
    for (int off = 16; off > 0; off >>= 1) {
#pragma unroll
        for (int i = 0; i < 8; i++)
            ss[i] += __shfl_xor_sync(0xFFFFFFFFu, ss[i], off);
    }

#pragma unroll
    for (int i = 0; i < 8; i++) {
        int mg = node0 + ty * 8 + i;
        if (mg < N_NODES) {
            float inv = 1.0f / fmaxf(sqrtf(ss[i]), 1e-12f);
            float4 o0, o1;
            o0.x = acc[i][0] * inv; o0.y = acc[i][1] * inv;
            o0.z = acc[i][2] * inv; o0.w = acc[i][3] * inv;
            o1.x = acc[i][4] * inv; o1.y = acc[i][5] * inv;
            o1.z = acc[i][6] * inv; o1.w = acc[i][7] * inv;
            float* op = out + (size_t)mg * C_OUT + tx * 8;
            *reinterpret_cast<float4*>(op)     = o0;
            *reinterpret_cast<float4*>(op + 4) = o1;
        }
    }
}

// ---------------- launch ------------------------------------------------------
extern "C" void kernel_launch(void* const* d_in, const int* in_sizes, int n_in,
                              void* d_out, int out_size) {
    const float*     x    = (const float*)d_in[0];      // [100000,128]
    const long long* ei   = (const long long*)d_in[1];  // [2,600000]
    const float*     W    = (const float*)d_in[2];      // [256,256]
    const float*     bias = (const float*)d_in[3];      // [1,256]
    float*           out  = (float*)d_out;              // [100000,256]

    detect_kernel<<<1, 1>>>(ei);

    {
        int tot = N_NODES * D_FEAT / 4;                 // 3.2M
        zero_kernel<<<(tot + 255) / 256, 256>>>();
    }

    {
        long long threads = (long long)E_EDGES * 32;
        scatter_kernel<<<(int)((threads + 255) / 256), 256>>>(x, ei);
    }

    {
        dim3 grid((N_NODES + BM - 1) / BM);             // 1563
        gemm_kernel<<<grid, 256>>>(x, W, bias, out);
    }
}